// round 5
// baseline (speedup 1.0000x reference)
#include <cuda_runtime.h>

// Problem shape (fixed by setup_inputs):
//   x1: [B=32, C=64, h=42, w=42]       float32
//   x2: [B=32, S=25, C=64, h=42, w=42] float32
//   out: [B, S*h*w] = [32, 44100]      float32
// out[b, s*HW + p] = sqrt( sum_c (x1[b,c,p] - x2[b,s,c,p])^2 )

#define B_   32
#define S_   25
#define C_   64
#define HW_  1764          // 42*42
#define HW4_ 441           // HW/4 (exact)

#define SG_  5             // supports per thread
#define NSG_ (S_ / SG_)    // 5 support-groups
#define TOTAL_ (B_ * NSG_ * HW4_)   // 70560 threads

#define PLANE4_ (C_ * HW4_)         // float4s per [C,h,w] slab = 28224

__global__ __launch_bounds__(256, 2)
void euclidean_block_kernel(const float* __restrict__ x1,
                            const float* __restrict__ x2,
                            float* __restrict__ out) {
    int t = blockIdx.x * blockDim.x + threadIdx.x;
    if (t >= TOTAL_) return;

    int p4   = t % HW4_;
    int rest = t / HW4_;
    int sg   = rest % NSG_;
    int b    = rest / NSG_;

    const float4* __restrict__ x1p =
        reinterpret_cast<const float4*>(x1) + (size_t)b * PLANE4_ + p4;
    // first of the 5 supports handled by this thread
    const float4* __restrict__ x2p =
        reinterpret_cast<const float4*>(x2) +
        ((size_t)b * S_ + sg * SG_) * PLANE4_ + p4;

    float4 acc[SG_];
    #pragma unroll
    for (int j = 0; j < SG_; ++j) acc[j] = make_float4(0.f, 0.f, 0.f, 0.f);

    // Double-buffered register pipeline over channels:
    // per channel: 1 x1 load + 5 x2 loads, consumed one stage behind.
    float4 a0, a1, v0[SG_], v1[SG_];

    // prologue: channel 0 -> buffer 0
    a0 = x1p[0];
    #pragma unroll
    for (int j = 0; j < SG_; ++j) v0[j] = __ldcs(&x2p[(size_t)j * PLANE4_]);

    #pragma unroll 4
    for (int c = 0; c < C_ - 2; c += 2) {
        // load channel c+1 -> buffer 1
        a1 = x1p[(c + 1) * HW4_];
        #pragma unroll
        for (int j = 0; j < SG_; ++j)
            v1[j] = __ldcs(&x2p[(size_t)j * PLANE4_ + (c + 1) * HW4_]);

        // consume channel c (buffer 0)
        #pragma unroll
        for (int j = 0; j < SG_; ++j) {
            float d0 = a0.x - v0[j].x;
            float d1 = a0.y - v0[j].y;
            float d2 = a0.z - v0[j].z;
            float d3 = a0.w - v0[j].w;
            acc[j].x = fmaf(d0, d0, acc[j].x);
            acc[j].y = fmaf(d1, d1, acc[j].y);
            acc[j].z = fmaf(d2, d2, acc[j].z);
            acc[j].w = fmaf(d3, d3, acc[j].w);
        }

        // load channel c+2 -> buffer 0
        a0 = x1p[(c + 2) * HW4_];
        #pragma unroll
        for (int j = 0; j < SG_; ++j)
            v0[j] = __ldcs(&x2p[(size_t)j * PLANE4_ + (c + 2) * HW4_]);

        // consume channel c+1 (buffer 1)
        #pragma unroll
        for (int j = 0; j < SG_; ++j) {
            float d0 = a1.x - v1[j].x;
            float d1 = a1.y - v1[j].y;
            float d2 = a1.z - v1[j].z;
            float d3 = a1.w - v1[j].w;
            acc[j].x = fmaf(d0, d0, acc[j].x);
            acc[j].y = fmaf(d1, d1, acc[j].y);
            acc[j].z = fmaf(d2, d2, acc[j].z);
            acc[j].w = fmaf(d3, d3, acc[j].w);
        }
    }

    // epilogue: buffer 0 holds channel 62; load+consume channel 63
    a1 = x1p[(C_ - 1) * HW4_];
    #pragma unroll
    for (int j = 0; j < SG_; ++j)
        v1[j] = __ldcs(&x2p[(size_t)j * PLANE4_ + (C_ - 1) * HW4_]);

    #pragma unroll
    for (int j = 0; j < SG_; ++j) {
        float d0 = a0.x - v0[j].x;
        float d1 = a0.y - v0[j].y;
        float d2 = a0.z - v0[j].z;
        float d3 = a0.w - v0[j].w;
        acc[j].x = fmaf(d0, d0, acc[j].x);
        acc[j].y = fmaf(d1, d1, acc[j].y);
        acc[j].z = fmaf(d2, d2, acc[j].z);
        acc[j].w = fmaf(d3, d3, acc[j].w);
    }
    #pragma unroll
    for (int j = 0; j < SG_; ++j) {
        float d0 = a1.x - v1[j].x;
        float d1 = a1.y - v1[j].y;
        float d2 = a1.z - v1[j].z;
        float d3 = a1.w - v1[j].w;
        acc[j].x = fmaf(d0, d0, acc[j].x);
        acc[j].y = fmaf(d1, d1, acc[j].y);
        acc[j].z = fmaf(d2, d2, acc[j].z);
        acc[j].w = fmaf(d3, d3, acc[j].w);
    }

    // write 5 outputs: (b*25 + sg*5 + j)*441 + p4  (float4 units)
    float4* __restrict__ op =
        reinterpret_cast<float4*>(out) +
        ((size_t)b * S_ + sg * SG_) * HW4_ + p4;
    #pragma unroll
    for (int j = 0; j < SG_; ++j) {
        float4 r;
        r.x = sqrtf(acc[j].x);
        r.y = sqrtf(acc[j].y);
        r.z = sqrtf(acc[j].z);
        r.w = sqrtf(acc[j].w);
        op[(size_t)j * HW4_] = r;
    }
}

extern "C" void kernel_launch(void* const* d_in, const int* in_sizes, int n_in,
                              void* d_out, int out_size) {
    const float* x1 = (const float*)d_in[0];
    const float* x2 = (const float*)d_in[1];
    float* out = (float*)d_out;

    const int threads = 256;
    const int blocks = (TOTAL_ + threads - 1) / threads;  // 276
    euclidean_block_kernel<<<blocks, threads>>>(x1, x2, out);
}